// round 11
// baseline (speedup 1.0000x reference)
#include <cuda_runtime.h>
#include <cuda_fp16.h>
#include <cstdint>

// patchEmbedding: (0) W->fp16 prep, (1) patch gather/pack fp16, (2) dense fp16 HMMA GEMM.
//   M = B*T = 131072, K = 256, N = 768
// K permuted per 32-half group: pair p (0..15) stored at position 4*(p&3)+(p>>2), so a
// thread's pairs {tq, tq+4, tq+8, tq+12} are contiguous -> one LDS.128 yields fragment
// registers for TWO m16n8k16 k-steps. Stage rows are dense 64B (addr = 16*lid: linear,
// conflict-free, no padding).
// GEMM CTA: 256 threads, 8 warps (4m x 2n), warp tile 32x64, CTA tile 128x128,
// 3-stage cp.async ring, 48KB smem -> 2 CTAs/SM (16 warps/SM: the r5-proven occupancy).

#define HW    512
#define TDIM  4096
#define EMBD  768
#define KTOT  256
#define BM    128
#define BN    128
#define NKI   8                            // 256 / 32 k-iterations
#define NST   3                            // cp.async stages
#define PADC  12

#define A_ST  (BM * 64)                    // 8192 B per A stage
#define B_ST  (BN * 64)                    // 8192 B per B stage
#define SM_A     0
#define SM_B     (NST * A_ST)              // 24576
#define SM_TOTAL (SM_B + NST * B_ST)       // 49152 B per CTA

__device__ __align__(16) __half g_Wh[EMBD * KTOT];        // fp16, k-permuted
__device__ __align__(16) __half g_Apack[131072 * KTOT];   // fp16, k-permuted

__device__ __forceinline__ uint32_t s2u(const void* p) {
    uint32_t a;
    asm("{ .reg .u64 t; cvta.to.shared.u64 t, %1; cvt.u32.u64 %0, t; }" : "=r"(a) : "l"(p));
    return a;
}
__device__ __forceinline__ void cp16(uint32_t dst, const void* src) {
    asm volatile("cp.async.ca.shared.global [%0], [%1], 16;" :: "r"(dst), "l"(src) : "memory");
}
__device__ __forceinline__ void mma_f16(float c[4], uint32_t a0, uint32_t a1,
                                        uint32_t a2, uint32_t a3,
                                        uint32_t b0, uint32_t b1) {
    asm volatile(
        "mma.sync.aligned.m16n8k16.row.col.f32.f16.f16.f32 "
        "{%0,%1,%2,%3}, {%4,%5,%6,%7}, {%8,%9}, {%0,%1,%2,%3};"
        : "+f"(c[0]), "+f"(c[1]), "+f"(c[2]), "+f"(c[3])
        : "r"(a0), "r"(a1), "r"(a2), "r"(a3), "r"(b0), "r"(b1));
}
// permute half index k within its 32-group: pair p=(k>>1)&15 -> 4*(p&3)+(p>>2)
__device__ __forceinline__ int kperm(int k) {
    int p = (k >> 1) & 15;
    return (k & ~31) | ((4 * (p & 3) + (p >> 2)) << 1) | (k & 1);
}

// ---- kernel 0: W -> fp16, k permuted ----
__global__ void prep_w(const float* __restrict__ W) {
    int i = blockIdx.x * blockDim.x + threadIdx.x;
    if (i >= EMBD * KTOT) return;
    g_Wh[(i & ~(KTOT - 1)) | kperm(i & (KTOT - 1))] = __float2half_rn(W[i]);
}

// ---- kernel 1: gather patches -> g_Apack (fp16, k permuted) ----
__global__ void __launch_bounds__(256, 4)
pack_a(const float* __restrict__ img,
       const int*   __restrict__ kp,
       const int*   __restrict__ sh)
{
    __shared__ int2 coord[128];
    const int tid = threadIdx.x;
    const int wid = tid >> 5;
    const int lid = tid & 31;
    const int m0  = blockIdx.x * 128;

    if (tid < 128) {
        int2 k = ((const int2*)kp)[m0 + tid];
        int2 s = ((const int2*)sh)[m0 + tid];
        int2 c;
        c.x = k.x + s.x - PADC;          // starts[...,0] = x
        c.y = k.y + s.y - PADC;          // starts[...,1] = y
        coord[tid] = c;
    }
    __syncthreads();

    const float* imgb = img + (size_t)(m0 / TDIM) * (HW * HW);
    const int pp = lid & 15;             // pair-slot within a 32-half group
    const int h  = pp >> 3;              // image-row parity within group
    const int jp = pp & 7;               // x-pair
    const int p  = h * 8 + jp;           // pair index within group
    const int kdst = (4 * (p & 3) + (p >> 2)) * 2;   // permuted half offset

    #pragma unroll 1
    for (int i = 0; i < 8; i++) {
        const int pat = i * 16 + wid * 2 + (lid >> 4);
        const int2 c = coord[pat];
        __half* orow = g_Apack + (size_t)(m0 + pat) * KTOT + kdst;
        #pragma unroll
        for (int kc = 0; kc < 8; kc++) {             // group = two image rows
            const int y  = c.y + kc * 2 + h;
            const int x0 = c.x + 2 * jp;
            float v0 = 0.f, v1 = 0.f;
            if ((unsigned)y < HW) {
                const float* rp = imgb + y * HW;
                if ((unsigned)(x0)     < HW) v0 = __ldg(rp + x0);
                if ((unsigned)(x0 + 1) < HW) v1 = __ldg(rp + x0 + 1);
            }
            *(__half2*)(orow + kc * 32) = __floats2half2_rn(v0, v1);
        }
    }
}

// ---- kernel 2: dense GEMM out = Apack @ Wh^T + bias ----
// 256 threads, 8 warps (4m x 2n), warp tile 32x64, full K accumulated in registers.
__global__ void __launch_bounds__(256, 2)
gemm_tc(const float* __restrict__ bias, float* __restrict__ out)
{
    extern __shared__ char smem[];
    const uint32_t sb = s2u(smem);
    const int tid = threadIdx.x;
    const int wid = tid >> 5;
    const int lid = tid & 31;
    const int m0  = blockIdx.y * BM;
    const int n0  = blockIdx.x * BN;

    const int wm = wid & 3;              // 0..3 : 32-row group
    const int wn = wid >> 2;             // 0..1 : 64-col group
    const int gq = lid >> 2;             // 0..7
    const int tq = lid & 3;              // 0..3

    // stage loader: A 128 rows x 64B + B 128 rows x 64B (k32 slice `ki`)
    #define LOAD(s, ki)                                                            \
        {                                                                          \
            _Pragma("unroll")                                                      \
            for (int i = 0; i < 2; i++) {                                          \
                const int idx = i * 256 + tid;                                     \
                const int row = idx >> 2, q = idx & 3;                             \
                cp16(sb + SM_A + (s) * A_ST + row * 64 + q * 16,                   \
                     g_Apack + (size_t)(m0 + row) * KTOT + (ki) * 32 + q * 8);     \
            }                                                                      \
            _Pragma("unroll")                                                      \
            for (int i = 0; i < 2; i++) {                                          \
                const int idx = i * 256 + tid;                                     \
                const int row = idx >> 2, q = idx & 3;                             \
                cp16(sb + SM_B + (s) * B_ST + row * 64 + q * 16,                   \
                     g_Wh + (size_t)(n0 + row) * KTOT + (ki) * 32 + q * 8);        \
            }                                                                      \
            asm volatile("cp.async.commit_group;" ::: "memory");                   \
        }

    LOAD(0, 0); LOAD(1, 1);

    float acc[2][8][4] = {};
    int s = 0;

    #pragma unroll 1
    for (int ki = 0; ki < NKI; ki++) {
        if (ki < NKI - 1)
            asm volatile("cp.async.wait_group 1;" ::: "memory");
        else
            asm volatile("cp.async.wait_group 0;" ::: "memory");
        __syncthreads();

        if (ki + 2 < NKI) {
            const int ns = (s + 2 >= NST) ? s + 2 - NST : s + 2;
            LOAD(ns, ki + 2);
        }

        const char* As = smem + SM_A + s * A_ST + (wm * 32) * 64;
        const char* Bs = smem + SM_B + s * B_ST + (wn * 64) * 64;

        // fragment loads: addr = 16*lid within each 16-row band -> conflict-free LDS.128
        uint4 alo[2], ahi[2];
        #pragma unroll
        for (int mt = 0; mt < 2; mt++) {
            alo[mt] = *(const uint4*)(As + (mt * 16 + gq) * 64 + tq * 16);
            ahi[mt] = *(const uint4*)(As + (mt * 16 + gq + 8) * 64 + tq * 16);
        }
        #pragma unroll
        for (int nt = 0; nt < 8; nt++) {
            const uint4 b = *(const uint4*)(Bs + (nt * 8 + gq) * 64 + tq * 16);
            #pragma unroll
            for (int mt = 0; mt < 2; mt++)    // k-step 0 of the group
                mma_f16(acc[mt][nt], alo[mt].x, ahi[mt].x, alo[mt].y, ahi[mt].y, b.x, b.y);
            #pragma unroll
            for (int mt = 0; mt < 2; mt++)    // k-step 1 of the group
                mma_f16(acc[mt][nt], alo[mt].z, ahi[mt].z, alo[mt].w, ahi[mt].w, b.z, b.w);
        }

        s = (s + 1 >= NST) ? 0 : s + 1;
    }

    // ---- epilogue: bias + float2 stores ----
    #pragma unroll
    for (int mt = 0; mt < 2; mt++) {
        const int r0 = m0 + wm * 32 + mt * 16 + gq;
        #pragma unroll
        for (int nt = 0; nt < 8; nt++) {
            const int col = n0 + wn * 64 + nt * 8 + tq * 2;
            const float2 bl = *(const float2*)(bias + col);
            float2 o0, o1;
            o0.x = acc[mt][nt][0] + bl.x;
            o0.y = acc[mt][nt][1] + bl.y;
            o1.x = acc[mt][nt][2] + bl.x;
            o1.y = acc[mt][nt][3] + bl.y;
            *(float2*)(out + (size_t)r0 * EMBD + col)       = o0;
            *(float2*)(out + (size_t)(r0 + 8) * EMBD + col) = o1;
        }
    }
}

extern "C" void kernel_launch(void* const* d_in, const int* in_sizes, int n_in,
                              void* d_out, int out_size)
{
    const float* img  = (const float*)d_in[0];   // [32,1,512,512] f32
    const int*   kp   = (const int*)  d_in[1];   // [32,4096,2] i32
    const int*   sh   = (const int*)  d_in[2];   // [32,4096,2] i32
    const float* Wlin = (const float*)d_in[3];   // [768,256] f32
    const float* blin = (const float*)d_in[4];   // [768] f32
    float*       out  = (float*)d_out;           // [32,4096,768] f32

    prep_w<<<(EMBD * KTOT + 255) / 256, 256>>>(Wlin);
    pack_a<<<(32 * TDIM) / 128, 256>>>(img, kp, sh);

    cudaFuncSetAttribute(gemm_tc,
                         cudaFuncAttributeMaxDynamicSharedMemorySize, SM_TOTAL);
    dim3 grid(EMBD / BN, (32 * TDIM) / BM);      // (6, 1024)
    gemm_tc<<<grid, 256, SM_TOTAL>>>(blin, out);
}

// round 14
// speedup vs baseline: 1.1097x; 1.1097x over previous
#include <cuda_runtime.h>
#include <cuda_fp16.h>
#include <cstdint>

// patchEmbedding: (0+1 merged) W->fp16 prep + patch gather/pack fp16, (2) fp16 HMMA GEMM.
//   M = B*T = 131072, K = 256, N = 768
// K pair-permuted per 16-group (pair p -> 2*(p&3)+(p>>2)) so each mma.m16n8k16
// fragment's half-pairs (2tq, 2tq+8) are adjacent -> single LDS.64 per fragment.
// GEMM: exact round-5 winner config: 256 thr, 8 warps (4m x 2n), warp tile 32x64,
// CTA 128x128, BK=64 halves, 2-stage cp.async, 160B smem rows, 2 CTAs/SM.

#define HW    512
#define TDIM  4096
#define EMBD  768
#define KTOT  256
#define BM    128
#define BN    128
#define BKH   64                          // halves per k-stage
#define NKC   4                           // 256 / 64
#define PADC  12

#define SROW  160                         // bytes per smem row (128B data + 32B pad)
#define MATB  (128 * SROW)                // 20480 B per matrix per stage
#define SM_A     0
#define SM_B     (2 * MATB)
#define SM_TOTAL (4 * MATB)               // 81920 B

__device__ __align__(16) __half g_Wh[EMBD * KTOT];        // fp16, k-permuted
__device__ __align__(16) __half g_Apack[131072 * KTOT];   // fp16, k-permuted

__device__ __forceinline__ uint32_t s2u(const void* p) {
    uint32_t a;
    asm("{ .reg .u64 t; cvta.to.shared.u64 t, %1; cvt.u32.u64 %0, t; }" : "=r"(a) : "l"(p));
    return a;
}
__device__ __forceinline__ void cp16(uint32_t dst, const void* src) {
    asm volatile("cp.async.ca.shared.global [%0], [%1], 16;" :: "r"(dst), "l"(src) : "memory");
}
__device__ __forceinline__ void mma_f16(float c[4], uint32_t a0, uint32_t a1,
                                        uint32_t a2, uint32_t a3,
                                        uint32_t b0, uint32_t b1) {
    asm volatile(
        "mma.sync.aligned.m16n8k16.row.col.f32.f16.f16.f32 "
        "{%0,%1,%2,%3}, {%4,%5,%6,%7}, {%8,%9}, {%0,%1,%2,%3};"
        : "+f"(c[0]), "+f"(c[1]), "+f"(c[2]), "+f"(c[3])
        : "r"(a0), "r"(a1), "r"(a2), "r"(a3), "r"(b0), "r"(b1));
}
// permute half index k within its 16-group: pair p=(k>>1)&7 -> 2*(p&3)+(p>>2)
__device__ __forceinline__ int kperm(int k) {
    int p = (k >> 1) & 7;
    return (k & ~15) | ((2 * (p & 3) + (p >> 2)) << 1) | (k & 1);
}

// ---- kernel 1: W prep (first 768 threads-groups) + gather patches -> g_Apack ----
__global__ void __launch_bounds__(256, 4)
pack_a(const float* __restrict__ img,
       const int*   __restrict__ kp,
       const int*   __restrict__ sh,
       const float* __restrict__ W)
{
    __shared__ int2 coord[BM];
    const int tid = threadIdx.x;
    const int wid = tid >> 5;
    const int lid = tid & 31;
    const int m0  = blockIdx.x * BM;

    // --- merged W prep: one element per thread for the first 768 blocks ---
    {
        const int i = blockIdx.x * 256 + tid;
        if (i < EMBD * KTOT)
            g_Wh[(i & ~(KTOT - 1)) | kperm(i & (KTOT - 1))] = __float2half_rn(W[i]);
    }

    if (tid < BM) {
        int2 k = ((const int2*)kp)[m0 + tid];
        int2 s = ((const int2*)sh)[m0 + tid];
        int2 c;
        c.x = k.x + s.x - PADC;          // starts[...,0] = x
        c.y = k.y + s.y - PADC;          // starts[...,1] = y
        coord[tid] = c;
    }
    __syncthreads();

    const float* imgb = img + (size_t)(m0 / TDIM) * (HW * HW);
    const int pp = lid & 15;             // pair-slot within a 32-half chunk
    const int h  = pp >> 3;              // image row within chunk
    const int jp = pp & 7;               // x-pair
    // permuted position of pair jp within its 16-group (group = row h)
    const int kdst = h * 16 + (2 * (jp & 3) + (jp >> 2)) * 2;

    #pragma unroll 1
    for (int i = 0; i < 8; i++) {
        const int p = i * 16 + wid * 2 + (lid >> 4);
        const int2 c = coord[p];
        __half* orow = g_Apack + (size_t)(m0 + p) * KTOT + kdst;
        #pragma unroll
        for (int kc = 0; kc < 8; kc++) {
            const int y  = c.y + kc * 2 + h;
            const int x0 = c.x + 2 * jp;
            float v0 = 0.f, v1 = 0.f;
            if ((unsigned)y < HW) {
                const float* rp = imgb + y * HW;
                if ((unsigned)(x0)     < HW) v0 = __ldg(rp + x0);
                if ((unsigned)(x0 + 1) < HW) v1 = __ldg(rp + x0 + 1);
            }
            *(__half2*)(orow + kc * 32) = __floats2half2_rn(v0, v1);
        }
    }
}

// ---- kernel 2: dense GEMM out = Apack @ Wh^T + bias (exact r5 winner) ----
__global__ void __launch_bounds__(256, 2)
gemm_tc(const float* __restrict__ bias, float* __restrict__ out)
{
    extern __shared__ char smem[];
    const uint32_t sb = s2u(smem);
    const int tid = threadIdx.x;
    const int wid = tid >> 5;
    const int lid = tid & 31;
    const int m0  = blockIdx.y * BM;
    const int n0  = blockIdx.x * BN;

    const int wm = wid & 3;              // 4 m-groups of 32 rows
    const int wn = wid >> 2;             // 2 n-groups of 64 cols
    const int gq = lid >> 2;             // 0..7
    const int tq = lid & 3;              // 0..3

    float acc[2][8][4] = {};

    // stage load: A rows 0..127 then B rows 0..127; 128B of halves per row
    #define LOAD_STAGE(buf, kc)                                                    \
        {                                                                          \
            _Pragma("unroll")                                                      \
            for (int i = 0; i < 8; i++) {                                          \
                const int idx = i * 256 + tid;          /* 0..2047 */              \
                const int row = (idx >> 3) & 127;                                  \
                const int q   = idx & 7;                                           \
                const uint32_t dst = sb + (i < 4 ? SM_A : SM_B) + (buf) * MATB     \
                                     + row * SROW + q * 16;                        \
                const __half* src = (i < 4)                                        \
                    ? g_Apack + (size_t)(m0 + row) * KTOT + (kc) * BKH + q * 8     \
                    : g_Wh   + (size_t)(n0 + row) * KTOT + (kc) * BKH + q * 8;     \
                cp16(dst, src);                                                    \
            }                                                                      \
            asm volatile("cp.async.commit_group;" ::: "memory");                   \
        }

    LOAD_STAGE(0, 0);
    LOAD_STAGE(1, 1);

    #pragma unroll 1
    for (int kc = 0; kc < NKC; kc++) {
        const int cur = kc & 1;
        if (kc == NKC - 1)
            asm volatile("cp.async.wait_group 0;" ::: "memory");
        else
            asm volatile("cp.async.wait_group 1;" ::: "memory");
        __syncthreads();

        const char* As = smem + SM_A + cur * MATB;
        const char* Bs = smem + SM_B + cur * MATB;

        #pragma unroll
        for (int ks = 0; ks < 4; ks++) {
            const int kb = ks * 32 + 8 * tq;             // byte offset of this thread's pairs
            uint2 a0[2], a1[2];
            #pragma unroll
            for (int mt = 0; mt < 2; mt++) {
                const int r = wm * 32 + mt * 16 + gq;
                a0[mt] = *(const uint2*)(As + r * SROW + kb);        // {a0a1, a4a5}
                a1[mt] = *(const uint2*)(As + (r + 8) * SROW + kb);  // {a2a3, a6a7}
            }
            #pragma unroll
            for (int nt = 0; nt < 8; nt++) {
                const int n = wn * 64 + nt * 8 + gq;
                const uint2 b = *(const uint2*)(Bs + n * SROW + kb); // {b0b1, b2b3}
                mma_f16(acc[0][nt], a0[0].x, a1[0].x, a0[0].y, a1[0].y, b.x, b.y);
                mma_f16(acc[1][nt], a0[1].x, a1[1].x, a0[1].y, a1[1].y, b.x, b.y);
            }
        }

        __syncthreads();
        if (kc + 2 < NKC) LOAD_STAGE(cur, kc + 2);
    }

    // ---- epilogue: bias + float2 stores ----
    #pragma unroll
    for (int mt = 0; mt < 2; mt++) {
        const int r0 = m0 + wm * 32 + mt * 16 + gq;
        #pragma unroll
        for (int nt = 0; nt < 8; nt++) {
            const int col = n0 + wn * 64 + nt * 8 + tq * 2;
            const float2 bl = *(const float2*)(bias + col);
            float2 o0, o1;
            o0.x = acc[mt][nt][0] + bl.x;
            o0.y = acc[mt][nt][1] + bl.y;
            o1.x = acc[mt][nt][2] + bl.x;
            o1.y = acc[mt][nt][3] + bl.y;
            *(float2*)(out + (size_t)r0 * EMBD + col)       = o0;
            *(float2*)(out + (size_t)(r0 + 8) * EMBD + col) = o1;
        }
    }
}

extern "C" void kernel_launch(void* const* d_in, const int* in_sizes, int n_in,
                              void* d_out, int out_size)
{
    const float* img  = (const float*)d_in[0];   // [32,1,512,512] f32
    const int*   kp   = (const int*)  d_in[1];   // [32,4096,2] i32
    const int*   sh   = (const int*)  d_in[2];   // [32,4096,2] i32
    const float* Wlin = (const float*)d_in[3];   // [768,256] f32
    const float* blin = (const float*)d_in[4];   // [768] f32
    float*       out  = (float*)d_out;           // [32,4096,768] f32

    pack_a<<<(32 * TDIM) / BM, 256>>>(img, kp, sh, Wlin);   // 1024 blocks (>= 768 for W prep)

    cudaFuncSetAttribute(gemm_tc,
                         cudaFuncAttributeMaxDynamicSharedMemorySize, SM_TOTAL);
    dim3 grid(EMBD / BN, (32 * TDIM) / BM);      // (6, 1024)
    gemm_tc<<<grid, 256, SM_TOTAL>>>(blin, out);
}

// round 15
// speedup vs baseline: 1.1863x; 1.0691x over previous
#include <cuda_runtime.h>
#include <cuda_fp16.h>
#include <cstdint>

// patchEmbedding: (1) merged W-prep + patch gather/pack fp16, (2) fp16 HMMA GEMM.
//   M = B*T = 131072, K = 256, N = 768
// A (g_Apack) is stored FRAGMENT-MAJOR: per 128-row block, layout is
//   [kc(4)][rb(4)][ks(4)][mt(2)][lane(32)][16B], where each lane's 16B are exactly
//   the m16n8k16 A-quad {a0,a1,a2,a3} for (rowblock rb, 16-row tile mt, k16 step ks).
// -> one LDS.128 per fragment, registers land in HMMA operand order (no MOV shuffles),
//    and the cp.async stage load is a contiguous 16KB block.
// B keeps the r5 scheme: k pair-permuted per 16-group (pair p -> 2*(p&3)+(p>>2)),
// 160B smem rows, uint2 (LDS.64) fragments already in operand order.
// GEMM: 256 thr, 8 warps (4m x 2n), warp tile 32x64, CTA 128x128, BK=64, 2-stage,
// 72KB smem -> 2 CTAs/SM.

#define HW    512
#define TDIM  4096
#define EMBD  768
#define KTOT  256
#define BM    128
#define BN    128
#define BKH   64                          // halves per k-stage
#define NKC   4                           // 256 / 64
#define PADC  12

#define A_ST  16384                       // bytes per A stage (dense, fragment-major)
#define SROW  160                         // B smem row bytes (128B data + 32B pad)
#define B_ST  (128 * SROW)                // 20480 B per B stage
#define SM_A     0
#define SM_B     (2 * A_ST)               // 32768
#define SM_TOTAL (SM_B + 2 * B_ST)        // 73728 B

__device__ __align__(16) __half g_Wh[EMBD * KTOT];        // fp16, k-permuted (B)
__device__ __align__(16) __half g_Apack[131072 * KTOT];   // fp16, fragment-major (A)

__device__ __forceinline__ uint32_t s2u(const void* p) {
    uint32_t a;
    asm("{ .reg .u64 t; cvta.to.shared.u64 t, %1; cvt.u32.u64 %0, t; }" : "=r"(a) : "l"(p));
    return a;
}
__device__ __forceinline__ void cp16(uint32_t dst, const void* src) {
    asm volatile("cp.async.ca.shared.global [%0], [%1], 16;" :: "r"(dst), "l"(src) : "memory");
}
__device__ __forceinline__ void mma_f16(float c[4], uint32_t a0, uint32_t a1,
                                        uint32_t a2, uint32_t a3,
                                        uint32_t b0, uint32_t b1) {
    asm volatile(
        "mma.sync.aligned.m16n8k16.row.col.f32.f16.f16.f32 "
        "{%0,%1,%2,%3}, {%4,%5,%6,%7}, {%8,%9}, {%0,%1,%2,%3};"
        : "+f"(c[0]), "+f"(c[1]), "+f"(c[2]), "+f"(c[3])
        : "r"(a0), "r"(a1), "r"(a2), "r"(a3), "r"(b0), "r"(b1));
}
// B permutation: half index k within its 16-group: pair p=(k>>1)&7 -> 2*(p&3)+(p>>2)
__device__ __forceinline__ int kperm(int k) {
    int p = (k >> 1) & 7;
    return (k & ~15) | ((2 * (p & 3) + (p >> 2)) << 1) | (k & 1);
}

// ---- kernel 1: merged W prep (first 768 blocks) + gather patches -> g_Apack ----
__global__ void __launch_bounds__(256, 4)
pack_a(const float* __restrict__ img,
       const int*   __restrict__ kp,
       const int*   __restrict__ sh,
       const float* __restrict__ W)
{
    __shared__ int2 coord[BM];
    const int tid = threadIdx.x;
    const int wid = tid >> 5;
    const int lid = tid & 31;
    const int m0  = blockIdx.x * BM;

    // --- merged W prep: one element per thread for the first 768 blocks ---
    {
        const int i = blockIdx.x * 256 + tid;
        if (i < EMBD * KTOT)
            g_Wh[(i & ~(KTOT - 1)) | kperm(i & (KTOT - 1))] = __float2half_rn(W[i]);
    }

    if (tid < BM) {
        int2 k = ((const int2*)kp)[m0 + tid];
        int2 s = ((const int2*)sh)[m0 + tid];
        int2 c;
        c.x = k.x + s.x - PADC;          // starts[...,0] = x
        c.y = k.y + s.y - PADC;          // starts[...,1] = y
        coord[tid] = c;
    }
    __syncthreads();

    const float* imgb = img + (size_t)(m0 / TDIM) * (HW * HW);
    const int pp = lid & 15;             // pixel-pair slot
    const int h  = pp >> 3;              // image-row parity within a 2-row chunk
    const int jp = pp & 7;               // x-pair
    const int tq = jp & 3;
    const int hi = jp >> 2;              // k-offset +8 half-pairs

    #pragma unroll 1
    for (int i = 0; i < 8; i++) {
        const int p = i * 16 + wid * 2 + (lid >> 4);   // patch 0..127
        const int2 c = coord[p];
        // fragment-major destination decomposition of patch row p
        const int rb = p >> 5;
        const int ri = p & 31;
        const int mt = (ri >> 4) & 1;
        const int gq = ri & 7;
        const int hs = (ri >> 3) & 1;
        // base offset (halves) within this 128-row block, excluding kcI terms
        const int off0 = rb * 2048 + mt * 256 + (gq * 4 + tq) * 8 + hi * 4 + hs * 2
                       + h * 512;
        __half* ob = g_Apack + (size_t)m0 * KTOT + off0;
        #pragma unroll
        for (int kcI = 0; kcI < 8; kcI++) {            // 8 chunks of 2 image rows
            const int y  = c.y + kcI * 2 + h;
            const int x0 = c.x + 2 * jp;
            float v0 = 0.f, v1 = 0.f;
            if ((unsigned)y < HW) {
                const float* rp = imgb + y * HW;
                if ((unsigned)(x0)     < HW) v0 = __ldg(rp + x0);
                if ((unsigned)(x0 + 1) < HW) v1 = __ldg(rp + x0 + 1);
            }
            const int koff = (kcI >> 1) * 8192 + (kcI & 1) * 1024;
            *(__half2*)(ob + koff) = __floats2half2_rn(v0, v1);
        }
    }
}

// ---- kernel 2: dense GEMM out = Apack @ Wh^T + bias ----
__global__ void __launch_bounds__(256, 2)
gemm_tc(const float* __restrict__ bias, float* __restrict__ out)
{
    extern __shared__ char smem[];
    const uint32_t sb = s2u(smem);
    const int tid = threadIdx.x;
    const int wid = tid >> 5;
    const int lid = tid & 31;
    const int m0  = blockIdx.y * BM;
    const int n0  = blockIdx.x * BN;

    const int wm = wid & 3;              // 4 m-groups of 32 rows (= rowblock rb)
    const int wn = wid >> 2;             // 2 n-groups of 64 cols
    const int gq = lid >> 2;             // 0..7
    const int tq = lid & 3;              // 0..3

    float acc[2][8][4] = {};

    // stage load: A = contiguous 16KB fragment-major block; B = 128 rows x 128B
    #define LOAD_STAGE(buf, kc)                                                    \
        {                                                                          \
            const char* asrc = (const char*)g_Apack + (size_t)m0 * 512             \
                               + (kc) * 16384;                                     \
            _Pragma("unroll")                                                      \
            for (int i = 0; i < 4; i++) {                                          \
                const int idx = i * 256 + tid;          /* 0..1023 */              \
                cp16(sb + SM_A + (buf) * A_ST + idx * 16, asrc + idx * 16);        \
            }                                                                      \
            _Pragma("unroll")                                                      \
            for (int i = 0; i < 4; i++) {                                          \
                const int idx = i * 256 + tid;          /* 0..1023 */              \
                const int row = idx >> 3;                                          \
                const int q   = idx & 7;                                           \
                cp16(sb + SM_B + (buf) * B_ST + row * SROW + q * 16,               \
                     g_Wh + (size_t)(n0 + row) * KTOT + (kc) * BKH + q * 8);       \
            }                                                                      \
            asm volatile("cp.async.commit_group;" ::: "memory");                   \
        }

    LOAD_STAGE(0, 0);
    LOAD_STAGE(1, 1);

    #pragma unroll 1
    for (int kc = 0; kc < NKC; kc++) {
        const int cur = kc & 1;
        if (kc == NKC - 1)
            asm volatile("cp.async.wait_group 0;" ::: "memory");
        else
            asm volatile("cp.async.wait_group 1;" ::: "memory");
        __syncthreads();

        // per-warp A base: fragment-major [rb=wm][ks][mt][lane]
        const char* As = smem + SM_A + cur * A_ST + wm * 4096 + lid * 16;
        const char* Bs = smem + SM_B + cur * B_ST + (wn * 64) * SROW;

        #pragma unroll
        for (int ks = 0; ks < 4; ks++) {
            const uint4 a0 = *(const uint4*)(As + ks * 1024);        // mt 0 quad
            const uint4 a1 = *(const uint4*)(As + ks * 1024 + 512);  // mt 1 quad
            const int kb = ks * 32 + 8 * tq;
            #pragma unroll
            for (int nt = 0; nt < 8; nt++) {
                const uint2 b = *(const uint2*)(Bs + (nt * 8 + gq) * SROW + kb);
                mma_f16(acc[0][nt], a0.x, a0.y, a0.z, a0.w, b.x, b.y);
                mma_f16(acc[1][nt], a1.x, a1.y, a1.z, a1.w, b.x, b.y);
            }
        }

        __syncthreads();
        if (kc + 2 < NKC) LOAD_STAGE(cur, kc + 2);
    }

    // ---- epilogue: bias + float2 stores ----
    #pragma unroll
    for (int mt = 0; mt < 2; mt++) {
        const int r0 = m0 + wm * 32 + mt * 16 + gq;
        #pragma unroll
        for (int nt = 0; nt < 8; nt++) {
            const int col = n0 + wn * 64 + nt * 8 + tq * 2;
            const float2 bl = *(const float2*)(bias + col);
            float2 o0, o1;
            o0.x = acc[mt][nt][0] + bl.x;
            o0.y = acc[mt][nt][1] + bl.y;
            o1.x = acc[mt][nt][2] + bl.x;
            o1.y = acc[mt][nt][3] + bl.y;
            *(float2*)(out + (size_t)r0 * EMBD + col)       = o0;
            *(float2*)(out + (size_t)(r0 + 8) * EMBD + col) = o1;
        }
    }
}

extern "C" void kernel_launch(void* const* d_in, const int* in_sizes, int n_in,
                              void* d_out, int out_size)
{
    const float* img  = (const float*)d_in[0];   // [32,1,512,512] f32
    const int*   kp   = (const int*)  d_in[1];   // [32,4096,2] i32
    const int*   sh   = (const int*)  d_in[2];   // [32,4096,2] i32
    const float* Wlin = (const float*)d_in[3];   // [768,256] f32
    const float* blin = (const float*)d_in[4];   // [768] f32
    float*       out  = (float*)d_out;           // [32,4096,768] f32

    pack_a<<<(32 * TDIM) / BM, 256>>>(img, kp, sh, Wlin);   // 1024 blocks

    cudaFuncSetAttribute(gemm_tc,
                         cudaFuncAttributeMaxDynamicSharedMemorySize, SM_TOTAL);
    dim3 grid(EMBD / BN, (32 * TDIM) / BM);      // (6, 1024)
    gemm_tc<<<grid, 256, SM_TOTAL>>>(blin, out);
}

// round 16
// speedup vs baseline: 1.2062x; 1.0168x over previous
#include <cuda_runtime.h>
#include <cuda_fp16.h>
#include <cstdint>

// patchEmbedding: (1) merged W-prep + patch gather/pack fp16, (2) fp16 HMMA GEMM.
//   M = B*T = 131072, K = 256, N = 768
// A (g_Apack) is FRAGMENT-MAJOR in global: per 128-row block,
//   [kc(4)][rb(4)][ks(4)][mt(2)][lane(32)][16B]; lane's 16B = m16n8k16 A-quad
//   {a0,a1,a2,a3}. GEMM loads A quads DIRECTLY from global via LDG.128 (no smem for A).
// B: fp16, k pair-permuted per 16-group (pair p -> 2*(p&3)+(p>>2)); smem 160B rows;
//   uint2 (LDS.64) fragments arrive in HMMA operand order.
// GEMM: 256 thr, 8 warps (4m x 2n), warp tile 32x64, CTA 128x128, BK=64, 2-stage B,
//   40KB smem -> 2 CTAs/SM.

#define HW    512
#define TDIM  4096
#define EMBD  768
#define KTOT  256
#define BM    128
#define BN    128
#define BKH   64                          // halves per k-stage
#define NKC   4                           // 256 / 64
#define PADC  12

#define SROW  160                         // B smem row bytes (128B data + 32B pad)
#define B_ST  (128 * SROW)                // 20480 B per B stage
#define SM_TOTAL (2 * B_ST)               // 40960 B

__device__ __align__(16) __half g_Wh[EMBD * KTOT];        // fp16, k-permuted (B)
__device__ __align__(16) __half g_Apack[131072 * KTOT];   // fp16, fragment-major (A)

__device__ __forceinline__ uint32_t s2u(const void* p) {
    uint32_t a;
    asm("{ .reg .u64 t; cvta.to.shared.u64 t, %1; cvt.u32.u64 %0, t; }" : "=r"(a) : "l"(p));
    return a;
}
__device__ __forceinline__ void cp16(uint32_t dst, const void* src) {
    asm volatile("cp.async.ca.shared.global [%0], [%1], 16;" :: "r"(dst), "l"(src) : "memory");
}
__device__ __forceinline__ void mma_f16(float c[4], uint32_t a0, uint32_t a1,
                                        uint32_t a2, uint32_t a3,
                                        uint32_t b0, uint32_t b1) {
    asm volatile(
        "mma.sync.aligned.m16n8k16.row.col.f32.f16.f16.f32 "
        "{%0,%1,%2,%3}, {%4,%5,%6,%7}, {%8,%9}, {%0,%1,%2,%3};"
        : "+f"(c[0]), "+f"(c[1]), "+f"(c[2]), "+f"(c[3])
        : "r"(a0), "r"(a1), "r"(a2), "r"(a3), "r"(b0), "r"(b1));
}
// B permutation: half index k within its 16-group: pair p=(k>>1)&7 -> 2*(p&3)+(p>>2)
__device__ __forceinline__ int kperm(int k) {
    int p = (k >> 1) & 7;
    return (k & ~15) | ((2 * (p & 3) + (p >> 2)) << 1) | (k & 1);
}

// ---- kernel 1: merged W prep (first 768 blocks) + gather patches -> g_Apack ----
__global__ void __launch_bounds__(256, 4)
pack_a(const float* __restrict__ img,
       const int*   __restrict__ kp,
       const int*   __restrict__ sh,
       const float* __restrict__ W)
{
    __shared__ int2 coord[BM];
    const int tid = threadIdx.x;
    const int wid = tid >> 5;
    const int lid = tid & 31;
    const int m0  = blockIdx.x * BM;

    // --- merged W prep: one element per thread for the first 768 blocks ---
    {
        const int i = blockIdx.x * 256 + tid;
        if (i < EMBD * KTOT)
            g_Wh[(i & ~(KTOT - 1)) | kperm(i & (KTOT - 1))] = __float2half_rn(W[i]);
    }

    if (tid < BM) {
        int2 k = ((const int2*)kp)[m0 + tid];
        int2 s = ((const int2*)sh)[m0 + tid];
        int2 c;
        c.x = k.x + s.x - PADC;          // starts[...,0] = x
        c.y = k.y + s.y - PADC;          // starts[...,1] = y
        coord[tid] = c;
    }
    __syncthreads();

    const float* imgb = img + (size_t)(m0 / TDIM) * (HW * HW);
    const int pp = lid & 15;             // pixel-pair slot
    const int h  = pp >> 3;              // image-row parity within a 2-row chunk
    const int jp = pp & 7;               // x-pair
    const int tq = jp & 3;
    const int hi = jp >> 2;              // k-offset +8 half-pairs

    #pragma unroll 1
    for (int i = 0; i < 8; i++) {
        const int p = i * 16 + wid * 2 + (lid >> 4);   // patch 0..127
        const int2 c = coord[p];
        // fragment-major destination decomposition of patch row p
        const int rb = p >> 5;
        const int ri = p & 31;
        const int mt = (ri >> 4) & 1;
        const int gq = ri & 7;
        const int hs = (ri >> 3) & 1;
        const int off0 = rb * 2048 + mt * 256 + (gq * 4 + tq) * 8 + hi * 4 + hs * 2
                       + h * 512;
        __half* ob = g_Apack + (size_t)m0 * KTOT + off0;
        #pragma unroll
        for (int kcI = 0; kcI < 8; kcI++) {            // 8 chunks of 2 image rows
            const int y  = c.y + kcI * 2 + h;
            const int x0 = c.x + 2 * jp;
            float v0 = 0.f, v1 = 0.f;
            if ((unsigned)y < HW) {
                const float* rp = imgb + y * HW;
                if ((unsigned)(x0)     < HW) v0 = __ldg(rp + x0);
                if ((unsigned)(x0 + 1) < HW) v1 = __ldg(rp + x0 + 1);
            }
            const int koff = (kcI >> 1) * 8192 + (kcI & 1) * 1024;
            *(__half2*)(ob + koff) = __floats2half2_rn(v0, v1);
        }
    }
}

// ---- kernel 2: dense GEMM out = Apack @ Wh^T + bias (A direct-from-global) ----
__global__ void __launch_bounds__(256, 2)
gemm_tc(const float* __restrict__ bias, float* __restrict__ out)
{
    extern __shared__ char smem[];
    const uint32_t sb = s2u(smem);
    const int tid = threadIdx.x;
    const int wid = tid >> 5;
    const int lid = tid & 31;
    const int m0  = blockIdx.y * BM;
    const int n0  = blockIdx.x * BN;

    const int wm = wid & 3;              // 4 m-groups of 32 rows (= rowblock rb)
    const int wn = wid >> 2;             // 2 n-groups of 64 cols
    const int gq = lid >> 2;             // 0..7
    const int tq = lid & 3;              // 0..3

    float acc[2][8][4] = {};

    // B stage load: 128 rows x 128B
    #define LOAD_B(buf, kc)                                                        \
        {                                                                          \
            _Pragma("unroll")                                                      \
            for (int i = 0; i < 4; i++) {                                          \
                const int idx = i * 256 + tid;          /* 0..1023 */              \
                const int row = idx >> 3;                                          \
                const int q   = idx & 7;                                           \
                cp16(sb + (buf) * B_ST + row * SROW + q * 16,                      \
                     g_Wh + (size_t)(n0 + row) * KTOT + (kc) * BKH + q * 8);       \
            }                                                                      \
            asm volatile("cp.async.commit_group;" ::: "memory");                   \
        }

    LOAD_B(0, 0);
    LOAD_B(1, 1);

    // per-warp A base in global (fragment-major)
    const char* Agw = (const char*)g_Apack + (size_t)m0 * 512 + wm * 4096 + lid * 16;

    #pragma unroll 1
    for (int kc = 0; kc < NKC; kc++) {
        const int cur = kc & 1;

        // ---- A quads for this k-iter: direct LDG.128, issued before the B wait ----
        uint4 aq[4][2];
        {
            const char* Ag = Agw + kc * 16384;
            #pragma unroll
            for (int ks = 0; ks < 4; ks++) {
                aq[ks][0] = __ldg((const uint4*)(Ag + ks * 1024));
                aq[ks][1] = __ldg((const uint4*)(Ag + ks * 1024 + 512));
            }
        }

        if (kc == NKC - 1)
            asm volatile("cp.async.wait_group 0;" ::: "memory");
        else
            asm volatile("cp.async.wait_group 1;" ::: "memory");
        __syncthreads();

        const char* Bs = smem + cur * B_ST + (wn * 64) * SROW;

        #pragma unroll
        for (int ks = 0; ks < 4; ks++) {
            const int kb = ks * 32 + 8 * tq;
            #pragma unroll
            for (int nt = 0; nt < 8; nt++) {
                const uint2 b = *(const uint2*)(Bs + (nt * 8 + gq) * SROW + kb);
                mma_f16(acc[0][nt], aq[ks][0].x, aq[ks][0].y, aq[ks][0].z, aq[ks][0].w,
                        b.x, b.y);
                mma_f16(acc[1][nt], aq[ks][1].x, aq[ks][1].y, aq[ks][1].z, aq[ks][1].w,
                        b.x, b.y);
            }
        }

        __syncthreads();
        if (kc + 2 < NKC) LOAD_B(cur, kc + 2);
    }

    // ---- epilogue: bias + float2 stores ----
    #pragma unroll
    for (int mt = 0; mt < 2; mt++) {
        const int r0 = m0 + wm * 32 + mt * 16 + gq;
        #pragma unroll
        for (int nt = 0; nt < 8; nt++) {
            const int col = n0 + wn * 64 + nt * 8 + tq * 2;
            const float2 bl = *(const float2*)(bias + col);
            float2 o0, o1;
            o0.x = acc[mt][nt][0] + bl.x;
            o0.y = acc[mt][nt][1] + bl.y;
            o1.x = acc[mt][nt][2] + bl.x;
            o1.y = acc[mt][nt][3] + bl.y;
            *(float2*)(out + (size_t)r0 * EMBD + col)       = o0;
            *(float2*)(out + (size_t)(r0 + 8) * EMBD + col) = o1;
        }
    }
}

extern "C" void kernel_launch(void* const* d_in, const int* in_sizes, int n_in,
                              void* d_out, int out_size)
{
    const float* img  = (const float*)d_in[0];   // [32,1,512,512] f32
    const int*   kp   = (const int*)  d_in[1];   // [32,4096,2] i32
    const int*   sh   = (const int*)  d_in[2];   // [32,4096,2] i32
    const float* Wlin = (const float*)d_in[3];   // [768,256] f32
    const float* blin = (const float*)d_in[4];   // [768] f32
    float*       out  = (float*)d_out;           // [32,4096,768] f32

    pack_a<<<(32 * TDIM) / BM, 256>>>(img, kp, sh, Wlin);   // 1024 blocks

    cudaFuncSetAttribute(gemm_tc,
                         cudaFuncAttributeMaxDynamicSharedMemorySize, SM_TOTAL);
    dim3 grid(EMBD / BN, (32 * TDIM) / BM);      // (6, 1024)
    gemm_tc<<<grid, 256, SM_TOTAL>>>(blin, out);
}

// round 17
// speedup vs baseline: 1.3555x; 1.1238x over previous
#include <cuda_runtime.h>
#include <cuda_fp16.h>
#include <cstdint>

// patchEmbedding: (1) merged W-prep + patch gather/pack fp16, (2) fp16 HMMA GEMM.
//   M = B*T = 131072, K = 256, N = 768
// A (g_Apack) is FRAGMENT-MAJOR in global: per 128-row block,
//   [kc(4)][rb(4)][ks(4)][mt(2)][lane(32)][16B]; lane's 16B = m16n8k16 A-quad.
//   GEMM loads A quads directly via LDG.128 (no smem for A).
// B: fp16, k pair-permuted per 16-group; FULL-K tile (128 rows x 512B) loaded into
//   smem ONCE per CTA -> exactly one wait+syncthreads in the whole mainloop; all
//   16 k16-steps then run barrier-free so warps cover each other's LDG latency.
// GEMM: 256 thr, 8 warps (4m x 2n), warp tile 32x64, CTA 128x128, 69.6KB smem,
//   2 CTAs/SM.

#define HW    512
#define TDIM  4096
#define EMBD  768
#define KTOT  256
#define BM    128
#define BN    128
#define NKC   4                           // 4 k-groups of 64 halves
#define PADC  12

#define SROW  544                         // B smem row bytes (512B data + 32B pad)
#define SM_TOTAL (128 * SROW)             // 69632 B (single full-K B tile)

__device__ __align__(16) __half g_Wh[EMBD * KTOT];        // fp16, k-permuted (B)
__device__ __align__(16) __half g_Apack[131072 * KTOT];   // fp16, fragment-major (A)

__device__ __forceinline__ uint32_t s2u(const void* p) {
    uint32_t a;
    asm("{ .reg .u64 t; cvta.to.shared.u64 t, %1; cvt.u32.u64 %0, t; }" : "=r"(a) : "l"(p));
    return a;
}
__device__ __forceinline__ void cp16(uint32_t dst, const void* src) {
    asm volatile("cp.async.ca.shared.global [%0], [%1], 16;" :: "r"(dst), "l"(src) : "memory");
}
__device__ __forceinline__ void mma_f16(float c[4], uint32_t a0, uint32_t a1,
                                        uint32_t a2, uint32_t a3,
                                        uint32_t b0, uint32_t b1) {
    asm volatile(
        "mma.sync.aligned.m16n8k16.row.col.f32.f16.f16.f32 "
        "{%0,%1,%2,%3}, {%4,%5,%6,%7}, {%8,%9}, {%0,%1,%2,%3};"
        : "+f"(c[0]), "+f"(c[1]), "+f"(c[2]), "+f"(c[3])
        : "r"(a0), "r"(a1), "r"(a2), "r"(a3), "r"(b0), "r"(b1));
}
// B permutation: half index k within its 16-group: pair p=(k>>1)&7 -> 2*(p&3)+(p>>2)
__device__ __forceinline__ int kperm(int k) {
    int p = (k >> 1) & 7;
    return (k & ~15) | ((2 * (p & 3) + (p >> 2)) << 1) | (k & 1);
}

// ---- kernel 1: merged W prep (first 768 blocks) + gather patches -> g_Apack ----
__global__ void __launch_bounds__(256, 4)
pack_a(const float* __restrict__ img,
       const int*   __restrict__ kp,
       const int*   __restrict__ sh,
       const float* __restrict__ W)
{
    __shared__ int2 coord[BM];
    const int tid = threadIdx.x;
    const int wid = tid >> 5;
    const int lid = tid & 31;
    const int m0  = blockIdx.x * BM;

    // --- merged W prep: one element per thread for the first 768 blocks ---
    {
        const int i = blockIdx.x * 256 + tid;
        if (i < EMBD * KTOT)
            g_Wh[(i & ~(KTOT - 1)) | kperm(i & (KTOT - 1))] = __float2half_rn(W[i]);
    }

    if (tid < BM) {
        int2 k = ((const int2*)kp)[m0 + tid];
        int2 s = ((const int2*)sh)[m0 + tid];
        int2 c;
        c.x = k.x + s.x - PADC;          // starts[...,0] = x
        c.y = k.y + s.y - PADC;          // starts[...,1] = y
        coord[tid] = c;
    }
    __syncthreads();

    const float* imgb = img + (size_t)(m0 / TDIM) * (HW * HW);
    const int pp = lid & 15;             // pixel-pair slot
    const int h  = pp >> 3;              // image-row parity within a 2-row chunk
    const int jp = pp & 7;               // x-pair
    const int tq = jp & 3;
    const int hi = jp >> 2;              // k-offset +8 half-pairs

    #pragma unroll 1
    for (int i = 0; i < 8; i++) {
        const int p = i * 16 + wid * 2 + (lid >> 4);   // patch 0..127
        const int2 c = coord[p];
        // fragment-major destination decomposition of patch row p
        const int rb = p >> 5;
        const int ri = p & 31;
        const int mt = (ri >> 4) & 1;
        const int gq = ri & 7;
        const int hs = (ri >> 3) & 1;
        const int off0 = rb * 2048 + mt * 256 + (gq * 4 + tq) * 8 + hi * 4 + hs * 2
                       + h * 512;
        __half* ob = g_Apack + (size_t)m0 * KTOT + off0;
        #pragma unroll
        for (int kcI = 0; kcI < 8; kcI++) {            // 8 chunks of 2 image rows
            const int y  = c.y + kcI * 2 + h;
            const int x0 = c.x + 2 * jp;
            float v0 = 0.f, v1 = 0.f;
            if ((unsigned)y < HW) {
                const float* rp = imgb + y * HW;
                if ((unsigned)(x0)     < HW) v0 = __ldg(rp + x0);
                if ((unsigned)(x0 + 1) < HW) v1 = __ldg(rp + x0 + 1);
            }
            const int koff = (kcI >> 1) * 8192 + (kcI & 1) * 1024;
            *(__half2*)(ob + koff) = __floats2half2_rn(v0, v1);
        }
    }
}

// ---- kernel 2: dense GEMM out = Apack @ Wh^T + bias ----
// Full-K B tile in smem (one sync); A quads from global; barrier-free mainloop.
__global__ void __launch_bounds__(256, 2)
gemm_tc(const float* __restrict__ bias, float* __restrict__ out)
{
    extern __shared__ char smem[];
    const uint32_t sb = s2u(smem);
    const int tid = threadIdx.x;
    const int wid = tid >> 5;
    const int lid = tid & 31;
    const int m0  = blockIdx.y * BM;
    const int n0  = blockIdx.x * BN;

    const int wm = wid & 3;              // 4 m-groups of 32 rows (= rowblock rb)
    const int wn = wid >> 2;             // 2 n-groups of 64 cols
    const int gq = lid >> 2;             // 0..7
    const int tq = lid & 3;              // 0..3

    // ---- B full-K load: 128 rows x 512B (16 cp16 per thread) ----
    {
        #pragma unroll
        for (int i = 0; i < 16; i++) {
            const int idx = i * 256 + tid;          // 0..4095
            const int row = idx >> 5;
            const int q   = idx & 31;
            cp16(sb + row * SROW + q * 16,
                 g_Wh + (size_t)(n0 + row) * KTOT + q * 8);
        }
        asm volatile("cp.async.commit_group;" ::: "memory");
    }

    // per-warp A base in global (fragment-major)
    const char* Agw = (const char*)g_Apack + (size_t)m0 * 512 + wm * 4096 + lid * 16;

    // prefetch kc=0 A quads before the B wait
    uint4 aq[4][2];
    #pragma unroll
    for (int ks = 0; ks < 4; ks++) {
        aq[ks][0] = __ldg((const uint4*)(Agw + ks * 1024));
        aq[ks][1] = __ldg((const uint4*)(Agw + ks * 1024 + 512));
    }

    asm volatile("cp.async.wait_group 0;" ::: "memory");
    __syncthreads();                     // the ONLY barrier in the mainloop

    float acc[2][8][4] = {};
    const char* Bs = smem + (wn * 64) * SROW;

    #pragma unroll 1
    for (int kc = 0; kc < NKC; kc++) {
        if (kc > 0) {
            const char* Ag = Agw + kc * 16384;
            #pragma unroll
            for (int ks = 0; ks < 4; ks++) {
                aq[ks][0] = __ldg((const uint4*)(Ag + ks * 1024));
                aq[ks][1] = __ldg((const uint4*)(Ag + ks * 1024 + 512));
            }
        }
        #pragma unroll
        for (int ks = 0; ks < 4; ks++) {
            const int kb = kc * 128 + ks * 32 + 8 * tq;    // byte offset in B row
            #pragma unroll
            for (int nt = 0; nt < 8; nt++) {
                const uint2 b = *(const uint2*)(Bs + (nt * 8 + gq) * SROW + kb);
                mma_f16(acc[0][nt], aq[ks][0].x, aq[ks][0].y, aq[ks][0].z, aq[ks][0].w,
                        b.x, b.y);
                mma_f16(acc[1][nt], aq[ks][1].x, aq[ks][1].y, aq[ks][1].z, aq[ks][1].w,
                        b.x, b.y);
            }
        }
    }

    // ---- epilogue: bias + float2 stores ----
    #pragma unroll
    for (int mt = 0; mt < 2; mt++) {
        const int r0 = m0 + wm * 32 + mt * 16 + gq;
        #pragma unroll
        for (int nt = 0; nt < 8; nt++) {
            const int col = n0 + wn * 64 + nt * 8 + tq * 2;
            const float2 bl = *(const float2*)(bias + col);
            float2 o0, o1;
            o0.x = acc[mt][nt][0] + bl.x;
            o0.y = acc[mt][nt][1] + bl.y;
            o1.x = acc[mt][nt][2] + bl.x;
            o1.y = acc[mt][nt][3] + bl.y;
            *(float2*)(out + (size_t)r0 * EMBD + col)       = o0;
            *(float2*)(out + (size_t)(r0 + 8) * EMBD + col) = o1;
        }
    }
}

extern "C" void kernel_launch(void* const* d_in, const int* in_sizes, int n_in,
                              void* d_out, int out_size)
{
    const float* img  = (const float*)d_in[0];   // [32,1,512,512] f32
    const int*   kp   = (const int*)  d_in[1];   // [32,4096,2] i32
    const int*   sh   = (const int*)  d_in[2];   // [32,4096,2] i32
    const float* Wlin = (const float*)d_in[3];   // [768,256] f32
    const float* blin = (const float*)d_in[4];   // [768] f32
    float*       out  = (float*)d_out;           // [32,4096,768] f32

    pack_a<<<(32 * TDIM) / BM, 256>>>(img, kp, sh, Wlin);   // 1024 blocks

    cudaFuncSetAttribute(gemm_tc,
                         cudaFuncAttributeMaxDynamicSharedMemorySize, SM_TOTAL);
    dim3 grid(EMBD / BN, (32 * TDIM) / BM);      // (6, 1024)
    gemm_tc<<<grid, 256, SM_TOTAL>>>(blin, out);
}